// round 3
// baseline (speedup 1.0000x reference)
#include <cuda_runtime.h>
#include <math.h>
#include <stdint.h>

// ---------------- problem constants ----------------
#define BATCH 32
#define NNODE 1024
#define NT    32768
#define DEG   8
#define NE    262144
#define F_IN  64
#define HIDC  128
#define EDIM  16
#define NR    16
#define HD    4
#define HDH   512
#define KEEP1 820
#define KEEP2 656
#define NEG_SLOPE 0.2f

typedef unsigned long long ull;

// ---------------- f32x2 packed helpers ----------------
__device__ __forceinline__ float f2lo(ull u) { return __uint_as_float((unsigned)u); }
__device__ __forceinline__ float f2hi(ull u) { return __uint_as_float((unsigned)(u >> 32)); }
__device__ __forceinline__ ull fdup(float s) {
    ull r; unsigned u = __float_as_uint(s);
    asm("mov.b64 %0, {%1, %1};" : "=l"(r) : "r"(u));
    return r;
}
#define FMA2(d, a, b) asm("fma.rn.f32x2 %0, %2, %3, %1;" : "=l"(d) : "l"(d), "l"(a), "l"(b))

// ---------------- device scratch ----------------
__device__ float g_xl[(size_t)NT * HDH];
__device__ float g_xr[(size_t)NT * HDH];
__device__ float g_h1[(size_t)NT * HIDC];
__device__ float g_h2[(size_t)NT * HIDC];
__device__ float g_score1[NT];
__device__ float g_score2[NT];
__device__ float g_gate[NT];
__device__ int   g_keep1[NT];
__device__ int   g_keep2[NT];
__device__ int   g_cnt[NT];
__device__ int   g_pos[NT];
__device__ int   g_row[NT + 1];
__device__ int   g_csr[NE];
__device__ float g_gmx[BATCH * HIDC];
__device__ float g_gav[BATCH * HIDC];

// ---------------- CSR build ----------------
__global__ void zero_kernel() {
    int i = blockIdx.x * blockDim.x + threadIdx.x;
    if (i < NT) { g_cnt[i] = 0; g_pos[i] = 0; }
}
__global__ void count_kernel(const int* __restrict__ dst) {
    int e = blockIdx.x * blockDim.x + threadIdx.x;
    if (e < NE) atomicAdd(&g_cnt[dst[e]], 1);
}
__global__ void scan_kernel() {
    __shared__ int s[1024];
    int t = threadIdx.x;
    int base = t * 32;
    int vals[32];
    int loc = 0;
#pragma unroll
    for (int j = 0; j < 32; j++) { vals[j] = g_cnt[base + j]; loc += vals[j]; }
    s[t] = loc;
    __syncthreads();
    for (int off = 1; off < 1024; off <<= 1) {
        int v = 0;
        if (t >= off) v = s[t - off];
        __syncthreads();
        s[t] += v;
        __syncthreads();
    }
    int run = s[t] - loc;
#pragma unroll
    for (int j = 0; j < 32; j++) { g_row[base + j] = run; run += vals[j]; }
    if (t == 1023) g_row[NT] = run;
}
__global__ void scatter_kernel(const int* __restrict__ dst) {
    int e = blockIdx.x * blockDim.x + threadIdx.x;
    if (e < NE) {
        int d = dst[e];
        int p = atomicAdd(&g_pos[d], 1);
        g_csr[g_row[d] + p] = e;
    }
}

// ---------------- SGEMM: f32x2, BM=128 BN=128 BK=16, double-buffered smem ----------------
// C0 = diag(gate)A @ W0 + b0 ; C1 = diag(gate)A @ W1 + b1. grid.x=8 (4 col-blocks each).
__global__ __launch_bounds__(256)
void sgemm2(const float* __restrict__ A,
            const float* __restrict__ W0, const float* __restrict__ W1,
            const float* __restrict__ bias0, const float* __restrict__ bias1,
            const float* __restrict__ gate,
            float* __restrict__ C0, float* __restrict__ C1, int K) {
    __shared__ float sA[2][16][128];
    __shared__ float sB[2][16][128];
    int tid = threadIdx.x;
    int which = blockIdx.x >> 2;
    const float* W = which ? W1 : W0;
    const float* bias = which ? bias1 : bias0;
    float* C = which ? C1 : C0;
    int col0 = (blockIdx.x & 3) * 128;
    int row0 = blockIdx.y * 128;
    int tr = tid >> 4, tc = tid & 15;

    int aidx0 = tid * 2, aidx1 = tid * 2 + 1;
    int ar0 = aidx0 >> 2, ak0 = (aidx0 & 3) * 4;
    int ar1 = aidx1 >> 2, ak1 = (aidx1 & 3) * 4;
    int bk0 = aidx0 >> 5, bc0 = (aidx0 & 31) * 4;
    int bk1 = aidx1 >> 5, bc1 = (aidx1 & 31) * 4;
    const float* Abase = A + (size_t)row0 * K;
    const float* Wbase = W + col0;
    float ga0 = 1.f, ga1 = 1.f;
    if (gate) { ga0 = gate[row0 + ar0]; ga1 = gate[row0 + ar1]; }

    ull acc[4][8];
#pragma unroll
    for (int p = 0; p < 4; p++)
#pragma unroll
        for (int j = 0; j < 8; j++) acc[p][j] = 0ull;

    float4 pa0, pa1, pb0, pb1;
    pa0 = *(const float4*)(Abase + (size_t)ar0 * K + ak0);
    pa1 = *(const float4*)(Abase + (size_t)ar1 * K + ak1);
    pb0 = *(const float4*)(Wbase + (size_t)bk0 * 512 + bc0);
    pb1 = *(const float4*)(Wbase + (size_t)bk1 * 512 + bc1);

    int buf = 0;
    sA[0][ak0 + 0][ar0] = pa0.x * ga0; sA[0][ak0 + 1][ar0] = pa0.y * ga0;
    sA[0][ak0 + 2][ar0] = pa0.z * ga0; sA[0][ak0 + 3][ar0] = pa0.w * ga0;
    sA[0][ak1 + 0][ar1] = pa1.x * ga1; sA[0][ak1 + 1][ar1] = pa1.y * ga1;
    sA[0][ak1 + 2][ar1] = pa1.z * ga1; sA[0][ak1 + 3][ar1] = pa1.w * ga1;
    *(float4*)&sB[0][bk0][bc0] = pb0;
    *(float4*)&sB[0][bk1][bc1] = pb1;
    __syncthreads();

    int ntiles = K >> 4;
    for (int t = 0; t < ntiles; t++) {
        bool hn = (t + 1) < ntiles;
        if (hn) {
            int kn = (t + 1) * 16;
            pa0 = *(const float4*)(Abase + (size_t)ar0 * K + kn + ak0);
            pa1 = *(const float4*)(Abase + (size_t)ar1 * K + kn + ak1);
            pb0 = *(const float4*)(Wbase + (size_t)(kn + bk0) * 512 + bc0);
            pb1 = *(const float4*)(Wbase + (size_t)(kn + bk1) * 512 + bc1);
        }
#pragma unroll
        for (int kk = 0; kk < 16; kk++) {
            ulonglong2 av0 = *(const ulonglong2*)&sA[buf][kk][tr * 8];
            ulonglong2 av1 = *(const ulonglong2*)&sA[buf][kk][tr * 8 + 4];
            float4 b0 = *(const float4*)&sB[buf][kk][tc * 8];
            float4 b1 = *(const float4*)&sB[buf][kk][tc * 8 + 4];
            ull a2[4] = {av0.x, av0.y, av1.x, av1.y};
            ull bd[8] = {fdup(b0.x), fdup(b0.y), fdup(b0.z), fdup(b0.w),
                         fdup(b1.x), fdup(b1.y), fdup(b1.z), fdup(b1.w)};
#pragma unroll
            for (int p = 0; p < 4; p++)
#pragma unroll
                for (int j = 0; j < 8; j++) FMA2(acc[p][j], a2[p], bd[j]);
        }
        if (hn) {
            int nb = buf ^ 1;
            sA[nb][ak0 + 0][ar0] = pa0.x * ga0; sA[nb][ak0 + 1][ar0] = pa0.y * ga0;
            sA[nb][ak0 + 2][ar0] = pa0.z * ga0; sA[nb][ak0 + 3][ar0] = pa0.w * ga0;
            sA[nb][ak1 + 0][ar1] = pa1.x * ga1; sA[nb][ak1 + 1][ar1] = pa1.y * ga1;
            sA[nb][ak1 + 2][ar1] = pa1.z * ga1; sA[nb][ak1 + 3][ar1] = pa1.w * ga1;
            *(float4*)&sB[nb][bk0][bc0] = pb0;
            *(float4*)&sB[nb][bk1][bc1] = pb1;
            __syncthreads();
            buf = nb;
        }
    }

    float4 bv0 = *(const float4*)(bias + col0 + tc * 8);
    float4 bv1 = *(const float4*)(bias + col0 + tc * 8 + 4);
    float bb[8] = {bv0.x, bv0.y, bv0.z, bv0.w, bv1.x, bv1.y, bv1.z, bv1.w};
#pragma unroll
    for (int i = 0; i < 8; i++) {
        int p = i >> 1, hf = i & 1;
        float v[8];
#pragma unroll
        for (int j = 0; j < 8; j++) v[j] = (hf ? f2hi(acc[p][j]) : f2lo(acc[p][j])) + bb[j];
        float* dst = C + (size_t)(row0 + tr * 8 + i) * 512 + col0 + tc * 8;
        *(float4*)dst = make_float4(v[0], v[1], v[2], v[3]);
        *(float4*)(dst + 4) = make_float4(v[4], v[5], v[6], v[7]);
    }
}

// ---------------- GATv2: warp/node, 4-edge chunks, no-max softmax, fused score ----------------
__global__ __launch_bounds__(128)
void gat_kernel(const float* __restrict__ xl, const float* __restrict__ xr,
                const float* __restrict__ ea_g, const float* __restrict__ We,
                const float* __restrict__ att, const float* __restrict__ bias,
                const float* __restrict__ pvec,
                const int* __restrict__ src, const int* __restrict__ kp,
                float* __restrict__ out, float* __restrict__ score) {
    __shared__ float sWe[16][512];
    __shared__ float sAtt[512];
    __shared__ float sEa[4][4][16];
    for (int i = threadIdx.x; i < 2048; i += 128)
        ((float4*)&sWe[0][0])[i] = ((const float4*)We)[i];
    if (threadIdx.x < 128) ((float4*)sAtt)[threadIdx.x] = ((const float4*)att)[threadIdx.x];
    __syncthreads();

    int warp = threadIdx.x >> 5, lane = threadIdx.x & 31;
    int node = blockIdx.x * 4 + warp;
    int l4 = lane * 4;

    float4 xrv[HD], attv[HD];
    ull acc[HD][2];
    float dh[HD];
#pragma unroll
    for (int h = 0; h < HD; h++) {
        xrv[h] = *(const float4*)(xr + (size_t)node * HDH + h * HIDC + l4);
        attv[h] = *(const float4*)(&sAtt[h * HIDC + l4]);
        acc[h][0] = 0ull; acc[h][1] = 0ull;
        dh[h] = 0.f;
    }

    bool okd = (kp == nullptr) || (kp[node] != 0);
    int beg = g_row[node];
    int end = okd ? g_row[node + 1] : beg;

    for (int base = beg; base < end; base += 4) {
        int nv = end - base;
        int ee = 0, ss = 0, vv = 0;
        if (lane < 4) {
            int okl = lane < nv;
            ee = g_csr[okl ? base + lane : base];
            ss = src[ee];
            vv = okl && (kp == nullptr || kp[ss] != 0);
        }
        int sid[4], val[4], eid[4];
#pragma unroll
        for (int e = 0; e < 4; e++) {
            eid[e] = __shfl_sync(0xffffffffu, ee, e);
            sid[e] = __shfl_sync(0xffffffffu, ss, e);
            val[e] = __shfl_sync(0xffffffffu, vv, e);
        }
        __syncwarp();
        if (lane < 16) {
            int e = lane >> 2, q = lane & 3;
            float4 v = *(const float4*)(ea_g + (size_t)eid[e] * EDIM + q * 4);
            *(float4*)&sEa[warp][e][q * 4] = v;
        }
        __syncwarp();

        ulonglong2 xlv[4][HD];
#pragma unroll
        for (int e = 0; e < 4; e++)
#pragma unroll
            for (int h = 0; h < HD; h++)
                xlv[e][h] = *(const ulonglong2*)(xl + (size_t)sid[e] * HDH + h * HIDC + l4);

#pragma unroll
        for (int h = 0; h < HD; h++) {
            ull ef[4][2];
#pragma unroll
            for (int e = 0; e < 4; e++) { ef[e][0] = 0ull; ef[e][1] = 0ull; }
#pragma unroll
            for (int k = 0; k < 16; k++) {
                ulonglong2 w2 = *(const ulonglong2*)&sWe[k][h * HIDC + l4];
#pragma unroll
                for (int e = 0; e < 4; e++) {
                    ull sd = fdup(sEa[warp][e][k]);
                    FMA2(ef[e][0], sd, w2.x);
                    FMA2(ef[e][1], sd, w2.y);
                }
            }
            float part[4];
#pragma unroll
            for (int e = 0; e < 4; e++) {
                float tx = f2lo(xlv[e][h].x) + xrv[h].x + f2lo(ef[e][0]);
                float ty = f2hi(xlv[e][h].x) + xrv[h].y + f2hi(ef[e][0]);
                float tz = f2lo(xlv[e][h].y) + xrv[h].z + f2lo(ef[e][1]);
                float tw = f2hi(xlv[e][h].y) + xrv[h].w + f2hi(ef[e][1]);
                tx = tx > 0.f ? tx : NEG_SLOPE * tx;
                ty = ty > 0.f ? ty : NEG_SLOPE * ty;
                tz = tz > 0.f ? tz : NEG_SLOPE * tz;
                tw = tw > 0.f ? tw : NEG_SLOPE * tw;
                part[e] = tx * attv[h].x + ty * attv[h].y + tz * attv[h].z + tw * attv[h].w;
            }
#pragma unroll
            for (int off = 16; off; off >>= 1)
#pragma unroll
                for (int e = 0; e < 4; e++)
                    part[e] += __shfl_xor_sync(0xffffffffu, part[e], off);
#pragma unroll
            for (int e = 0; e < 4; e++) {
                float w = val[e] ? __expf(part[e]) : 0.f;   // logits bounded; no max needed
                dh[h] += w;
                ull wd = fdup(w);
                FMA2(acc[h][0], wd, xlv[e][h].x);
                FMA2(acc[h][1], wd, xlv[e][h].y);
            }
        }
        __syncwarp();
    }

    float r[HD];
#pragma unroll
    for (int h = 0; h < HD; h++) r[h] = 1.f / (dh[h] + 1e-16f);
    float ox = 0.f, oy = 0.f, oz = 0.f, ow = 0.f;
#pragma unroll
    for (int h = 0; h < HD; h++) {
        ox += f2lo(acc[h][0]) * r[h];
        oy += f2hi(acc[h][0]) * r[h];
        oz += f2lo(acc[h][1]) * r[h];
        ow += f2hi(acc[h][1]) * r[h];
    }
    float4 bv = *(const float4*)(bias + l4);
    float4 o;
    o.x = fmaxf(0.25f * ox + bv.x, 0.f);
    o.y = fmaxf(0.25f * oy + bv.y, 0.f);
    o.z = fmaxf(0.25f * oz + bv.z, 0.f);
    o.w = fmaxf(0.25f * ow + bv.w, 0.f);
    *(float4*)(out + (size_t)node * HIDC + l4) = o;

    // fused topk score: (h . p) / ||p||
    float4 pv = *(const float4*)(pvec + l4);
    float pn = pv.x * pv.x + pv.y * pv.y + pv.z * pv.z + pv.w * pv.w;
    float s = o.x * pv.x + o.y * pv.y + o.z * pv.z + o.w * pv.w;
#pragma unroll
    for (int off = 16; off; off >>= 1) {
        pn += __shfl_xor_sync(0xffffffffu, pn, off);
        s += __shfl_xor_sync(0xffffffffu, s, off);
    }
    if (lane == 0) score[node] = s / (sqrtf(pn) + 1e-16f);
}

// ---------------- gate vector: g = tanh(score) ----------------
__global__ void gate_vec(const float* __restrict__ score, float* __restrict__ g) {
    int i = blockIdx.x * blockDim.x + threadIdx.x;
    if (i < NT) g[i] = tanhf(score[i]);
}

// ---------------- per-graph top-k via bitonic sort ----------------
__global__ __launch_bounds__(512)
void topk_kernel(const float* __restrict__ score, const int* __restrict__ mask,
                 int Kkeep, int* __restrict__ keep) {
    __shared__ unsigned long long sk[NNODE];
    int g = blockIdx.x, t = threadIdx.x;
    for (int i = t; i < NNODE; i += 512) {
        int node = g * NNODE + i;
        float s = (mask && !mask[node]) ? -INFINITY : score[node];
        unsigned u = __float_as_uint(s);
        u = (u & 0x80000000u) ? ~u : (u | 0x80000000u);
        sk[i] = ((unsigned long long)u << 32) | (unsigned)(0xFFFFFFFFu - (unsigned)i);
    }
    for (int size = 2; size <= NNODE; size <<= 1) {
        for (int stride = size >> 1; stride > 0; stride >>= 1) {
            __syncthreads();
            int lo = 2 * t - (t & (stride - 1));
            bool desc = ((lo & size) == 0);
            unsigned long long a = sk[lo], b = sk[lo + stride];
            bool sw = desc ? (a < b) : (a > b);
            if (sw) { sk[lo] = b; sk[lo + stride] = a; }
        }
    }
    __syncthreads();
    for (int r = t; r < NNODE; r += 512) {
        int li = (int)(0xFFFFFFFFu - (unsigned)(sk[r] & 0xFFFFFFFFull));
        keep[g * NNODE + li] = (r < Kkeep) ? 1 : 0;
    }
}

// ---------------- global max / mean pool ----------------
__global__ __launch_bounds__(1024)
void pool_kernel(const float* __restrict__ h2, const float* __restrict__ score2) {
    __shared__ float sg[NNODE];
    __shared__ unsigned char skp[NNODE];
    __shared__ float rmx[8][HIDC];
    __shared__ float rsm[8][HIDC];
    int b = blockIdx.x, t = threadIdx.x;
    {
        int node = b * NNODE + t;
        int k = g_keep2[node];
        skp[t] = (unsigned char)k;
        sg[t] = k ? tanhf(score2[node]) : 0.f;
    }
    __syncthreads();
    int c = t & 127, sl = t >> 7;
    float mx = -INFINITY, sm = 0.f;
    for (int i = sl; i < NNODE; i += 8) {
        if (skp[i]) {
            float v = h2[(size_t)(b * NNODE + i) * HIDC + c] * sg[i];
            mx = fmaxf(mx, v);
            sm += v;
        }
    }
    rmx[sl][c] = mx; rsm[sl][c] = sm;
    __syncthreads();
    if (t < HIDC) {
        float m = rmx[0][t], s = rsm[0][t];
#pragma unroll
        for (int j = 1; j < 8; j++) { m = fmaxf(m, rmx[j][t]); s += rsm[j][t]; }
        g_gmx[b * HIDC + t] = m;
        g_gav[b * HIDC + t] = s / (float)KEEP2;
    }
}

// ---------------- final MLP ----------------
__global__ __launch_bounds__(128)
void mlp_kernel(const float* __restrict__ action,
                const float* __restrict__ Wf1, const float* __restrict__ bf1,
                const float* __restrict__ Wf2, const float* __restrict__ bf2,
                const float* __restrict__ Wf3, const float* __restrict__ bf3,
                float* __restrict__ out) {
    __shared__ float sz[2 * HIDC + NR];
    __shared__ float s1[HIDC];
    __shared__ float sred[HIDC];
    int b = blockIdx.x, c = threadIdx.x;
    sz[c] = g_gmx[b * HIDC + c];
    sz[HIDC + c] = g_gav[b * HIDC + c];
    if (c < NR) sz[2 * HIDC + c] = action[b * NR + c];
    __syncthreads();
    float a = bf1[c];
    for (int k = 0; k < 2 * HIDC + NR; k++) a = fmaf(sz[k], Wf1[k * HIDC + c], a);
    s1[c] = fmaxf(a, 0.f);
    __syncthreads();
    float a2 = bf2[c];
    for (int k = 0; k < HIDC; k++) a2 = fmaf(s1[k], Wf2[k * HIDC + c], a2);
    sred[c] = fmaxf(a2, 0.f) * Wf3[c];
    __syncthreads();
    for (int off = 64; off; off >>= 1) {
        if (c < off) sred[c] += sred[c + off];
        __syncthreads();
    }
    if (c == 0) out[b] = sred[0] + bf3[0];
}

// ---------------- launch ----------------
extern "C" void kernel_launch(void* const* d_in, const int* in_sizes, int n_in,
                              void* d_out, int out_size) {
    const float* x      = (const float*)d_in[0];
    const float* ea     = (const float*)d_in[1];
    const float* action = (const float*)d_in[2];
    const float* W1l    = (const float*)d_in[3];
    const float* b1l    = (const float*)d_in[4];
    const float* W1r    = (const float*)d_in[5];
    const float* b1r    = (const float*)d_in[6];
    const float* W1e    = (const float*)d_in[7];
    const float* att1   = (const float*)d_in[8];
    const float* bias1  = (const float*)d_in[9];
    const float* W2l    = (const float*)d_in[10];
    const float* b2l    = (const float*)d_in[11];
    const float* W2r    = (const float*)d_in[12];
    const float* b2r    = (const float*)d_in[13];
    const float* W2e    = (const float*)d_in[14];
    const float* att2   = (const float*)d_in[15];
    const float* bias2  = (const float*)d_in[16];
    const float* p1     = (const float*)d_in[17];
    const float* p2     = (const float*)d_in[18];
    const float* Wf1    = (const float*)d_in[19];
    const float* bf1    = (const float*)d_in[20];
    const float* Wf2    = (const float*)d_in[21];
    const float* bf2    = (const float*)d_in[22];
    const float* Wf3    = (const float*)d_in[23];
    const float* bf3    = (const float*)d_in[24];
    const int*   ei     = (const int*)d_in[25];
    const int* src = ei;
    const int* dst = ei + NE;
    float* out = (float*)d_out;

    float *xl, *xr, *h1, *h2, *s1, *s2, *gt;
    int *k1p, *k2p;
    cudaGetSymbolAddress((void**)&xl,  g_xl);
    cudaGetSymbolAddress((void**)&xr,  g_xr);
    cudaGetSymbolAddress((void**)&h1,  g_h1);
    cudaGetSymbolAddress((void**)&h2,  g_h2);
    cudaGetSymbolAddress((void**)&s1,  g_score1);
    cudaGetSymbolAddress((void**)&s2,  g_score2);
    cudaGetSymbolAddress((void**)&gt,  g_gate);
    cudaGetSymbolAddress((void**)&k1p, g_keep1);
    cudaGetSymbolAddress((void**)&k2p, g_keep2);

    // CSR by dst
    zero_kernel<<<NT / 256, 256>>>();
    count_kernel<<<NE / 256, 256>>>(dst);
    scan_kernel<<<1, 1024>>>();
    scatter_kernel<<<NE / 256, 256>>>(dst);

    dim3 ggrid(8, NT / 128);
    // layer 1
    sgemm2<<<ggrid, 256>>>(x, W1l, W1r, b1l, b1r, nullptr, xl, xr, F_IN);
    gat_kernel<<<NT / 4, 128>>>(xl, xr, ea, W1e, att1, bias1, p1, src, nullptr, h1, s1);
    // pool 1
    gate_vec<<<NT / 256, 256>>>(s1, gt);
    topk_kernel<<<BATCH, 512>>>(s1, nullptr, KEEP1, k1p);
    // layer 2 (gate fused into A load)
    sgemm2<<<ggrid, 256>>>(h1, W2l, W2r, b2l, b2r, gt, xl, xr, HIDC);
    gat_kernel<<<NT / 4, 128>>>(xl, xr, ea, W2e, att2, bias2, p2, src, k1p, h2, s2);
    // pool 2
    topk_kernel<<<BATCH, 512>>>(s2, k1p, KEEP2, k2p);
    // readout
    pool_kernel<<<BATCH, 1024>>>(h2, s2);
    mlp_kernel<<<BATCH, 128>>>(action, Wf1, bf1, Wf2, bf2, Wf3, bf3, out);
}

// round 5
// speedup vs baseline: 1.0749x; 1.0749x over previous
#include <cuda_runtime.h>
#include <math.h>
#include <stdint.h>

// ---------------- problem constants ----------------
#define BATCH 32
#define NNODE 1024
#define NT    32768
#define DEG   8
#define NE    262144
#define F_IN  64
#define HIDC  128
#define EDIM  16
#define NR    16
#define HD    4
#define HDH   512
#define KEEP1 820
#define KEEP2 656
#define NEG_SLOPE 0.2f

typedef unsigned long long ull;

// ---------------- f32x2 packed helpers ----------------
__device__ __forceinline__ float f2lo(ull u) { return __uint_as_float((unsigned)u); }
__device__ __forceinline__ float f2hi(ull u) { return __uint_as_float((unsigned)(u >> 32)); }
__device__ __forceinline__ ull fdup(float s) {
    ull r; unsigned u = __float_as_uint(s);
    asm("mov.b64 %0, {%1, %1};" : "=l"(r) : "r"(u));
    return r;
}
#define FMA2(d, a, b) asm("fma.rn.f32x2 %0, %2, %3, %1;" : "=l"(d) : "l"(d), "l"(a), "l"(b))

// ---------------- device scratch ----------------
__device__ float g_xl[(size_t)NT * HDH];
__device__ float g_xr[(size_t)NT * HDH];
__device__ float g_h1[(size_t)NT * HIDC];
__device__ float g_h2[(size_t)NT * HIDC];
__device__ float g_score1[NT];
__device__ float g_score2[NT];
__device__ float g_gate[NT];
__device__ int   g_keep1[NT];
__device__ int   g_keep2[NT];
__device__ int   g_cnt[NT];
__device__ int   g_pos[NT];
__device__ int   g_row[NT + 1];
__device__ int   g_csr[NE];
__device__ float g_gmx[BATCH * HIDC];
__device__ float g_gav[BATCH * HIDC];

// ---------------- CSR build ----------------
__global__ void zero_kernel() {
    int i = blockIdx.x * blockDim.x + threadIdx.x;
    if (i < NT) { g_cnt[i] = 0; g_pos[i] = 0; }
}
__global__ void count_kernel(const int* __restrict__ dst) {
    int e = blockIdx.x * blockDim.x + threadIdx.x;
    if (e < NE) atomicAdd(&g_cnt[dst[e]], 1);
}
__global__ void scan_kernel() {
    __shared__ int s[1024];
    int t = threadIdx.x;
    int base = t * 32;
    int vals[32];
    int loc = 0;
#pragma unroll
    for (int j = 0; j < 32; j++) { vals[j] = g_cnt[base + j]; loc += vals[j]; }
    s[t] = loc;
    __syncthreads();
    for (int off = 1; off < 1024; off <<= 1) {
        int v = 0;
        if (t >= off) v = s[t - off];
        __syncthreads();
        s[t] += v;
        __syncthreads();
    }
    int run = s[t] - loc;
#pragma unroll
    for (int j = 0; j < 32; j++) { g_row[base + j] = run; run += vals[j]; }
    if (t == 1023) g_row[NT] = run;
}
__global__ void scatter_kernel(const int* __restrict__ dst) {
    int e = blockIdx.x * blockDim.x + threadIdx.x;
    if (e < NE) {
        int d = dst[e];
        int p = atomicAdd(&g_pos[d], 1);
        g_csr[g_row[d] + p] = e;
    }
}

// ---------------- SGEMM v3: f32x2, BM=128 BN=128 BK=16, 128 thr, 16x8/thread ----------------
// C0 = diag(gate)A @ W0 + b0 ; C1 = diag(gate)A @ W1 + b1. grid.x = 8.
__global__ __launch_bounds__(128)
void sgemm3(const float* __restrict__ A,
            const float* __restrict__ W0, const float* __restrict__ W1,
            const float* __restrict__ bias0, const float* __restrict__ bias1,
            const float* __restrict__ gate,
            float* __restrict__ C0, float* __restrict__ C1, int K) {
    __shared__ float sA[2][16][128];
    __shared__ float sB[2][16][128];
    int tid = threadIdx.x;
    int which = blockIdx.x >> 2;
    const float* W = which ? W1 : W0;
    const float* bias = which ? bias1 : bias0;
    float* C = which ? C1 : C0;
    int col0 = (blockIdx.x & 3) * 128;
    int row0 = blockIdx.y * 128;
    int tr = tid >> 4;   // 0..7  -> rows tr*16 .. +15
    int tc = tid & 15;   // 0..15 -> cols tc*8 .. +7

    const float* Arow = A + (size_t)(row0 + tid) * K;   // this thread's A row
    float ga = gate ? gate[row0 + tid] : 1.f;
    const float* Wbase = W + col0;
    int bk[4], bc[4];
#pragma unroll
    for (int i = 0; i < 4; i++) { int idx = tid * 4 + i; bk[i] = idx >> 5; bc[i] = (idx & 31) * 4; }

    ull acc[8][8];
#pragma unroll
    for (int p = 0; p < 8; p++)
#pragma unroll
        for (int j = 0; j < 8; j++) acc[p][j] = 0ull;

    float4 pa[4], pb[4];
#pragma unroll
    for (int i = 0; i < 4; i++) {
        pa[i] = *(const float4*)(Arow + i * 4);
        pb[i] = *(const float4*)(Wbase + (size_t)bk[i] * 512 + bc[i]);
    }
    int buf = 0;
#pragma unroll
    for (int i = 0; i < 4; i++) {
        sA[0][i * 4 + 0][tid] = pa[i].x * ga;
        sA[0][i * 4 + 1][tid] = pa[i].y * ga;
        sA[0][i * 4 + 2][tid] = pa[i].z * ga;
        sA[0][i * 4 + 3][tid] = pa[i].w * ga;
        *(float4*)&sB[0][bk[i]][bc[i]] = pb[i];
    }
    __syncthreads();

    int ntiles = K >> 4;
    for (int t = 0; t < ntiles; t++) {
        bool hn = (t + 1) < ntiles;
        if (hn) {
            int kn = (t + 1) * 16;
#pragma unroll
            for (int i = 0; i < 4; i++) {
                pa[i] = *(const float4*)(Arow + kn + i * 4);
                pb[i] = *(const float4*)(Wbase + (size_t)(kn + bk[i]) * 512 + bc[i]);
            }
        }
#pragma unroll
        for (int kk = 0; kk < 16; kk++) {
            ulonglong2 a0 = *(const ulonglong2*)&sA[buf][kk][tr * 16];
            ulonglong2 a1 = *(const ulonglong2*)&sA[buf][kk][tr * 16 + 4];
            ulonglong2 a2v = *(const ulonglong2*)&sA[buf][kk][tr * 16 + 8];
            ulonglong2 a3 = *(const ulonglong2*)&sA[buf][kk][tr * 16 + 12];
            float4 b0 = *(const float4*)&sB[buf][kk][tc * 8];
            float4 b1 = *(const float4*)&sB[buf][kk][tc * 8 + 4];
            ull ar[8] = {a0.x, a0.y, a1.x, a1.y, a2v.x, a2v.y, a3.x, a3.y};
            ull bd[8] = {fdup(b0.x), fdup(b0.y), fdup(b0.z), fdup(b0.w),
                         fdup(b1.x), fdup(b1.y), fdup(b1.z), fdup(b1.w)};
#pragma unroll
            for (int p = 0; p < 8; p++)
#pragma unroll
                for (int j = 0; j < 8; j++) FMA2(acc[p][j], ar[p], bd[j]);
        }
        if (hn) {
            int nb = buf ^ 1;
#pragma unroll
            for (int i = 0; i < 4; i++) {
                sA[nb][i * 4 + 0][tid] = pa[i].x * ga;
                sA[nb][i * 4 + 1][tid] = pa[i].y * ga;
                sA[nb][i * 4 + 2][tid] = pa[i].z * ga;
                sA[nb][i * 4 + 3][tid] = pa[i].w * ga;
                *(float4*)&sB[nb][bk[i]][bc[i]] = pb[i];
            }
            __syncthreads();
            buf = nb;
        }
    }

    float4 bv0 = *(const float4*)(bias + col0 + tc * 8);
    float4 bv1 = *(const float4*)(bias + col0 + tc * 8 + 4);
    float bb[8] = {bv0.x, bv0.y, bv0.z, bv0.w, bv1.x, bv1.y, bv1.z, bv1.w};
#pragma unroll
    for (int r = 0; r < 16; r++) {
        int p = r >> 1, hf = r & 1;
        float v[8];
#pragma unroll
        for (int j = 0; j < 8; j++) v[j] = (hf ? f2hi(acc[p][j]) : f2lo(acc[p][j])) + bb[j];
        float* dst = C + (size_t)(row0 + tr * 16 + r) * 512 + col0 + tc * 8;
        *(float4*)dst = make_float4(v[0], v[1], v[2], v[3]);
        *(float4*)(dst + 4) = make_float4(v[4], v[5], v[6], v[7]);
    }
}

// ---------------- GATv2 (register-resident, no-max softmax, fused score) ----------------
#define EAC(e, k) (((k) & 3) == 0 ? eav[e][(k) >> 2].x : ((k) & 3) == 1 ? eav[e][(k) >> 2].y \
                   : ((k) & 3) == 2 ? eav[e][(k) >> 2].z : eav[e][(k) >> 2].w)

__global__ __launch_bounds__(128)
void gat_kernel(const float* __restrict__ xl, const float* __restrict__ xr,
                const float* __restrict__ ea_g, const float* __restrict__ We,
                const float* __restrict__ att, const float* __restrict__ bias,
                const float* __restrict__ pvec,
                const int* __restrict__ src, const int* __restrict__ kp,
                float* __restrict__ out, float* __restrict__ score) {
    __shared__ float sWe[16][512];
    __shared__ float sAtt[512];
    for (int i = threadIdx.x; i < 2048; i += 128)
        ((float4*)&sWe[0][0])[i] = ((const float4*)We)[i];
    if (threadIdx.x < 128) ((float4*)sAtt)[threadIdx.x] = ((const float4*)att)[threadIdx.x];
    __syncthreads();

    int warp = threadIdx.x >> 5, lane = threadIdx.x & 31;
    int node = blockIdx.x * 4 + warp;
    int l4 = lane * 4;

    float4 xrv[HD], attv[HD];
    ull acc[HD][2];
    float dh[HD];
#pragma unroll
    for (int h = 0; h < HD; h++) {
        xrv[h] = *(const float4*)(xr + (size_t)node * HDH + h * HIDC + l4);
        attv[h] = *(const float4*)(&sAtt[h * HIDC + l4]);
        acc[h][0] = 0ull; acc[h][1] = 0ull;
        dh[h] = 0.f;
    }

    bool okd = (kp == nullptr) || (kp[node] != 0);
    int beg = g_row[node];
    int end = okd ? g_row[node + 1] : beg;

    for (int base = beg; base < end; base += 4) {
        int nv = end - base;
        int sid[4]; bool val[4];
        float4 eav[4][4];
#pragma unroll
        for (int e = 0; e < 4; e++) {
            bool v = e < nv;
            int ee = g_csr[v ? base + e : base];
            int ss = src[ee];
            if (kp && !kp[ss]) v = false;
            sid[e] = ss; val[e] = v;
            const float4* p = (const float4*)(ea_g + (size_t)ee * EDIM);
            eav[e][0] = p[0]; eav[e][1] = p[1]; eav[e][2] = p[2]; eav[e][3] = p[3];
        }
#pragma unroll
        for (int h = 0; h < HD; h++) {
            ull ef[4][2];
#pragma unroll
            for (int e = 0; e < 4; e++) { ef[e][0] = 0ull; ef[e][1] = 0ull; }
#pragma unroll
            for (int k = 0; k < 16; k++) {
                ulonglong2 w2 = *(const ulonglong2*)&sWe[k][h * HIDC + l4];
#pragma unroll
                for (int e = 0; e < 4; e++) {
                    ull sd = fdup(EAC(e, k));
                    FMA2(ef[e][0], sd, w2.x);
                    FMA2(ef[e][1], sd, w2.y);
                }
            }
            ulonglong2 xlv[4];
            float part[4];
#pragma unroll
            for (int e = 0; e < 4; e++) {
                ulonglong2 xv = *(const ulonglong2*)(xl + (size_t)sid[e] * HDH + h * HIDC + l4);
                xlv[e] = xv;
                float tx = f2lo(xv.x) + xrv[h].x + f2lo(ef[e][0]);
                float ty = f2hi(xv.x) + xrv[h].y + f2hi(ef[e][0]);
                float tz = f2lo(xv.y) + xrv[h].z + f2lo(ef[e][1]);
                float tw = f2hi(xv.y) + xrv[h].w + f2hi(ef[e][1]);
                tx = tx > 0.f ? tx : NEG_SLOPE * tx;
                ty = ty > 0.f ? ty : NEG_SLOPE * ty;
                tz = tz > 0.f ? tz : NEG_SLOPE * tz;
                tw = tw > 0.f ? tw : NEG_SLOPE * tw;
                part[e] = tx * attv[h].x + ty * attv[h].y + tz * attv[h].z + tw * attv[h].w;
            }
#pragma unroll
            for (int off = 16; off; off >>= 1)
#pragma unroll
                for (int e = 0; e < 4; e++)
                    part[e] += __shfl_xor_sync(0xffffffffu, part[e], off);
#pragma unroll
            for (int e = 0; e < 4; e++) {
                float w = val[e] ? __expf(part[e]) : 0.f;   // logits bounded; exact softmax
                dh[h] += w;
                ull wd = fdup(w);
                FMA2(acc[h][0], wd, xlv[e].x);
                FMA2(acc[h][1], wd, xlv[e].y);
            }
        }
    }

    float r[HD];
#pragma unroll
    for (int h = 0; h < HD; h++) r[h] = 1.f / (dh[h] + 1e-16f);
    float ox = 0.f, oy = 0.f, oz = 0.f, ow = 0.f;
#pragma unroll
    for (int h = 0; h < HD; h++) {
        ox += f2lo(acc[h][0]) * r[h];
        oy += f2hi(acc[h][0]) * r[h];
        oz += f2lo(acc[h][1]) * r[h];
        ow += f2hi(acc[h][1]) * r[h];
    }
    float4 bv = *(const float4*)(bias + l4);
    float4 o;
    o.x = fmaxf(0.25f * ox + bv.x, 0.f);
    o.y = fmaxf(0.25f * oy + bv.y, 0.f);
    o.z = fmaxf(0.25f * oz + bv.z, 0.f);
    o.w = fmaxf(0.25f * ow + bv.w, 0.f);
    *(float4*)(out + (size_t)node * HIDC + l4) = o;

    // fused topk score: (h . p) / ||p||
    float4 pv = *(const float4*)(pvec + l4);
    float pn = pv.x * pv.x + pv.y * pv.y + pv.z * pv.z + pv.w * pv.w;
    float s = o.x * pv.x + o.y * pv.y + o.z * pv.z + o.w * pv.w;
#pragma unroll
    for (int off = 16; off; off >>= 1) {
        pn += __shfl_xor_sync(0xffffffffu, pn, off);
        s += __shfl_xor_sync(0xffffffffu, s, off);
    }
    if (lane == 0) score[node] = s / (sqrtf(pn) + 1e-16f);
}

// ---------------- gate vector: g = tanh(score) ----------------
__global__ void gate_vec(const float* __restrict__ score, float* __restrict__ g) {
    int i = blockIdx.x * blockDim.x + threadIdx.x;
    if (i < NT) g[i] = tanhf(score[i]);
}

// ---------------- per-graph top-k via bitonic sort ----------------
__global__ __launch_bounds__(512)
void topk_kernel(const float* __restrict__ score, const int* __restrict__ mask,
                 int Kkeep, int* __restrict__ keep) {
    __shared__ unsigned long long sk[NNODE];
    int g = blockIdx.x, t = threadIdx.x;
    for (int i = t; i < NNODE; i += 512) {
        int node = g * NNODE + i;
        float s = (mask && !mask[node]) ? -INFINITY : score[node];
        unsigned u = __float_as_uint(s);
        u = (u & 0x80000000u) ? ~u : (u | 0x80000000u);
        sk[i] = ((unsigned long long)u << 32) | (unsigned)(0xFFFFFFFFu - (unsigned)i);
    }
    for (int size = 2; size <= NNODE; size <<= 1) {
        for (int stride = size >> 1; stride > 0; stride >>= 1) {
            __syncthreads();
            int lo = 2 * t - (t & (stride - 1));
            bool desc = ((lo & size) == 0);
            unsigned long long a = sk[lo], b = sk[lo + stride];
            bool sw = desc ? (a < b) : (a > b);
            if (sw) { sk[lo] = b; sk[lo + stride] = a; }
        }
    }
    __syncthreads();
    for (int r = t; r < NNODE; r += 512) {
        int li = (int)(0xFFFFFFFFu - (unsigned)(sk[r] & 0xFFFFFFFFull));
        keep[g * NNODE + li] = (r < Kkeep) ? 1 : 0;
    }
}

// ---------------- global max / mean pool ----------------
__global__ __launch_bounds__(1024)
void pool_kernel(const float* __restrict__ h2, const float* __restrict__ score2) {
    __shared__ float sg[NNODE];
    __shared__ unsigned char skp[NNODE];
    __shared__ float rmx[8][HIDC];
    __shared__ float rsm[8][HIDC];
    int b = blockIdx.x, t = threadIdx.x;
    {
        int node = b * NNODE + t;
        int k = g_keep2[node];
        skp[t] = (unsigned char)k;
        sg[t] = k ? tanhf(score2[node]) : 0.f;
    }
    __syncthreads();
    int c = t & 127, sl = t >> 7;
    float mx = -INFINITY, sm = 0.f;
    for (int i = sl; i < NNODE; i += 8) {
        if (skp[i]) {
            float v = h2[(size_t)(b * NNODE + i) * HIDC + c] * sg[i];
            mx = fmaxf(mx, v);
            sm += v;
        }
    }
    rmx[sl][c] = mx; rsm[sl][c] = sm;
    __syncthreads();
    if (t < HIDC) {
        float m = rmx[0][t], s = rsm[0][t];
#pragma unroll
        for (int j = 1; j < 8; j++) { m = fmaxf(m, rmx[j][t]); s += rsm[j][t]; }
        g_gmx[b * HIDC + t] = m;
        g_gav[b * HIDC + t] = s / (float)KEEP2;
    }
}

// ---------------- final MLP ----------------
__global__ __launch_bounds__(128)
void mlp_kernel(const float* __restrict__ action,
                const float* __restrict__ Wf1, const float* __restrict__ bf1,
                const float* __restrict__ Wf2, const float* __restrict__ bf2,
                const float* __restrict__ Wf3, const float* __restrict__ bf3,
                float* __restrict__ out) {
    __shared__ float sz[2 * HIDC + NR];
    __shared__ float s1[HIDC];
    __shared__ float sred[HIDC];
    int b = blockIdx.x, c = threadIdx.x;
    sz[c] = g_gmx[b * HIDC + c];
    sz[HIDC + c] = g_gav[b * HIDC + c];
    if (c < NR) sz[2 * HIDC + c] = action[b * NR + c];
    __syncthreads();
    float a = bf1[c];
    for (int k = 0; k < 2 * HIDC + NR; k++) a = fmaf(sz[k], Wf1[k * HIDC + c], a);
    s1[c] = fmaxf(a, 0.f);
    __syncthreads();
    float a2 = bf2[c];
    for (int k = 0; k < HIDC; k++) a2 = fmaf(s1[k], Wf2[k * HIDC + c], a2);
    sred[c] = fmaxf(a2, 0.f) * Wf3[c];
    __syncthreads();
    for (int off = 64; off; off >>= 1) {
        if (c < off) sred[c] += sred[c + off];
        __syncthreads();
    }
    if (c == 0) out[b] = sred[0] + bf3[0];
}

// ---------------- launch ----------------
extern "C" void kernel_launch(void* const* d_in, const int* in_sizes, int n_in,
                              void* d_out, int out_size) {
    const float* x      = (const float*)d_in[0];
    const float* ea     = (const float*)d_in[1];
    const float* action = (const float*)d_in[2];
    const float* W1l    = (const float*)d_in[3];
    const float* b1l    = (const float*)d_in[4];
    const float* W1r    = (const float*)d_in[5];
    const float* b1r    = (const float*)d_in[6];
    const float* W1e    = (const float*)d_in[7];
    const float* att1   = (const float*)d_in[8];
    const float* bias1  = (const float*)d_in[9];
    const float* W2l    = (const float*)d_in[10];
    const float* b2l    = (const float*)d_in[11];
    const float* W2r    = (const float*)d_in[12];
    const float* b2r    = (const float*)d_in[13];
    const float* W2e    = (const float*)d_in[14];
    const float* att2   = (const float*)d_in[15];
    const float* bias2  = (const float*)d_in[16];
    const float* p1     = (const float*)d_in[17];
    const float* p2     = (const float*)d_in[18];
    const float* Wf1    = (const float*)d_in[19];
    const float* bf1    = (const float*)d_in[20];
    const float* Wf2    = (const float*)d_in[21];
    const float* bf2    = (const float*)d_in[22];
    const float* Wf3    = (const float*)d_in[23];
    const float* bf3    = (const float*)d_in[24];
    const int*   ei     = (const int*)d_in[25];
    const int* src = ei;
    const int* dst = ei + NE;
    float* out = (float*)d_out;

    float *xl, *xr, *h1, *h2, *s1, *s2, *gt;
    int *k1p, *k2p;
    cudaGetSymbolAddress((void**)&xl,  g_xl);
    cudaGetSymbolAddress((void**)&xr,  g_xr);
    cudaGetSymbolAddress((void**)&h1,  g_h1);
    cudaGetSymbolAddress((void**)&h2,  g_h2);
    cudaGetSymbolAddress((void**)&s1,  g_score1);
    cudaGetSymbolAddress((void**)&s2,  g_score2);
    cudaGetSymbolAddress((void**)&gt,  g_gate);
    cudaGetSymbolAddress((void**)&k1p, g_keep1);
    cudaGetSymbolAddress((void**)&k2p, g_keep2);

    // CSR by dst
    zero_kernel<<<NT / 256, 256>>>();
    count_kernel<<<NE / 256, 256>>>(dst);
    scan_kernel<<<1, 1024>>>();
    scatter_kernel<<<NE / 256, 256>>>(dst);

    dim3 ggrid(8, NT / 128);
    // layer 1
    sgemm3<<<ggrid, 128>>>(x, W1l, W1r, b1l, b1r, nullptr, xl, xr, F_IN);
    gat_kernel<<<NT / 4, 128>>>(xl, xr, ea, W1e, att1, bias1, p1, src, nullptr, h1, s1);
    // pool 1
    gate_vec<<<NT / 256, 256>>>(s1, gt);
    topk_kernel<<<BATCH, 512>>>(s1, nullptr, KEEP1, k1p);
    // layer 2 (gate fused into A load)
    sgemm3<<<ggrid, 128>>>(h1, W2l, W2r, b2l, b2r, gt, xl, xr, HIDC);
    gat_kernel<<<NT / 4, 128>>>(xl, xr, ea, W2e, att2, bias2, p2, src, k1p, h2, s2);
    // pool 2
    topk_kernel<<<BATCH, 512>>>(s2, k1p, KEEP2, k2p);
    // readout
    pool_kernel<<<BATCH, 1024>>>(h2, s2);
    mlp_kernel<<<BATCH, 128>>>(action, Wf1, bf1, Wf2, bf2, Wf3, bf3, out);
}